// round 12
// baseline (speedup 1.0000x reference)
#include <cuda_runtime.h>
#include <math.h>

#define BATCH 128
#define SEQ   1024
#define INP   7
#define HID   64
#define OUTD  500
#define MTOT  (BATCH*SEQ)   // 131072
#define HSP   20

typedef unsigned long long u64;
typedef unsigned int u32;

__device__ float g_hT[(size_t)HID * MTOT];   // h transposed: g_hT[k][b*SEQ+t]

// ---- f32x2 packed helpers (lstm) ----
__device__ __forceinline__ u64 ffma2(u64 a, u64 b, u64 c) {
    u64 d;
    asm("fma.rn.f32x2 %0, %1, %2, %3;" : "=l"(d) : "l"(a), "l"(b), "l"(c));
    return d;
}
__device__ __forceinline__ u64 fadd2(u64 a, u64 b) {
    u64 d;
    asm("add.rn.f32x2 %0, %1, %2;" : "=l"(d) : "l"(a), "l"(b));
    return d;
}
__device__ __forceinline__ void unpack2(u64 v, float& lo, float& hi) {
    u32 l, h;
    asm("mov.b64 {%0, %1}, %2;" : "=r"(l), "=r"(h) : "l"(v));
    lo = __uint_as_float(l); hi = __uint_as_float(h);
}
__device__ __forceinline__ float tanhf_fast(float x) {
    float y;
    asm("tanh.approx.f32 %0, %1;" : "=f"(y) : "f"(x));
    return y;
}
// ---- tf32 helpers (fc) ----
__device__ __forceinline__ u32 cvt_tf32(float x) {
    u32 r; asm("cvt.rna.tf32.f32 %0, %1;" : "=r"(r) : "f"(x)); return r;
}
__device__ __forceinline__ void mma_tf32(float* d,
    u32 a0, u32 a1, u32 a2, u32 a3, u32 b0, u32 b1)
{
    asm volatile(
        "mma.sync.aligned.m16n8k8.row.col.f32.tf32.tf32.f32 "
        "{%0,%1,%2,%3}, {%4,%5,%6,%7}, {%8,%9}, {%0,%1,%2,%3};"
        : "+f"(d[0]), "+f"(d[1]), "+f"(d[2]), "+f"(d[3])
        : "r"(a0), "r"(a1), "r"(a2), "r"(a3), "r"(b0), "r"(b1));
}

// ---------------------------------------------------------------------------
// LSTM recurrence, split-k: 512 threads/CTA, one CTA per batch.
// thread = (hh = tid>>3, gate = (tid>>1)&3, half = tid&1).
// Each thread does HALF the dot product (16 FFMA2, depth-4 chains),
// partner reduce via shfl_xor(1), gate exchange via 8-lane-group shuffles.
// 4 warps/SMSP at unchanged per-SM work -> latency holes covered.
// ---------------------------------------------------------------------------
__global__ __launch_bounds__(512, 1)
void lstm_kernel(const float* __restrict__ x,
                 const float* __restrict__ W_ih,
                 const float* __restrict__ W_hh,
                 const float* __restrict__ b_ih,
                 const float* __restrict__ b_hh)
{
    __shared__ float xs[SEQ * INP];                      // 28 KB
    __shared__ __align__(16) float hbuf[2][HID];
    __shared__ __align__(16) float hstage[2][HID][HSP];  // 10 KB

    const int b    = blockIdx.x;
    const int tid  = threadIdx.x;
    const int hh   = tid >> 3;
    const int gate = (tid >> 1) & 3;
    const int half = tid & 1;
    const int row  = gate * HID + hh;
    const int lane = tid & 31;
    const int l8   = lane & ~7;        // base lane of 8-lane (4 gate x 2 half) group

    // stage x[b] (1792 float4, 512 threads)
    {
        const float4* src = (const float4*)(x + (size_t)b * SEQ * INP);
        float4* dst = (float4*)xs;
        #pragma unroll
        for (int i = 0; i < 4; ++i) {
            int idx = tid + i*512;
            if (idx < (SEQ*INP)/4) dst[idx] = src[idx];
        }
    }

    // W_hh half-row -> packed registers (16 x f32x2)
    u64 w2[HID/4];
    {
        const ulonglong2* wr =
            (const ulonglong2*)(W_hh + (size_t)row * HID + half * (HID/2));
        #pragma unroll
        for (int i = 0; i < HID/8; ++i) {
            ulonglong2 v = wr[i];
            w2[2*i+0] = v.x; w2[2*i+1] = v.y;
        }
    }
    float wih[INP];
    #pragma unroll
    for (int i = 0; i < INP; ++i) wih[i] = W_ih[row*INP + i];
    const float bias = b_ih[row] + b_hh[row];

    const float scale = (gate == 2) ? 1.0f : 0.5f;
    const float off   = (gate == 2) ? 0.0f : 0.5f;

    if (tid < HID) hbuf[0][tid] = 0.0f;
    float c = 0.0f;
    __syncthreads();

    float xacc = bias;
    #pragma unroll
    for (int i = 0; i < INP; ++i) xacc = fmaf(xs[i], wih[i], xacc);

    int cur = 0;
    for (int t = 0; t < SEQ; ++t) {
        // half dot product: 8 LDS.128, 16 FFMA2 in 4 depth-4 chains
        const ulonglong2* hv =
            (const ulonglong2*)(hbuf[cur] + half * (HID/2));
        u64 a0 = 0ull, a1 = 0ull, a2 = 0ull, a3 = 0ull;
        #pragma unroll
        for (int j = 0; j < 2; ++j) {
            ulonglong2 h0 = hv[4*j+0];
            ulonglong2 h1 = hv[4*j+1];
            ulonglong2 h2 = hv[4*j+2];
            ulonglong2 h3 = hv[4*j+3];
            a0 = ffma2(h0.x, w2[8*j+0], a0);
            a1 = ffma2(h0.y, w2[8*j+1], a1);
            a2 = ffma2(h1.x, w2[8*j+2], a2);
            a3 = ffma2(h1.y, w2[8*j+3], a3);
            a0 = ffma2(h2.x, w2[8*j+4], a0);
            a1 = ffma2(h2.y, w2[8*j+5], a1);
            a2 = ffma2(h3.x, w2[8*j+6], a2);
            a3 = ffma2(h3.y, w2[8*j+7], a3);
        }
        u64 s = fadd2(fadd2(a0, a1), fadd2(a2, a3));
        float slo, shi; unpack2(s, slo, shi);
        float p = slo + shi;
        p += __shfl_xor_sync(0xffffffffu, p, 1);   // combine k-halves
        float pre = xacc + p;

        float act = fmaf(scale, tanhf_fast(scale * pre), off);

        float ig = __shfl_sync(0xffffffffu, act, l8+0);
        float fg = __shfl_sync(0xffffffffu, act, l8+2);
        float gg = __shfl_sync(0xffffffffu, act, l8+4);
        float og = __shfl_sync(0xffffffffu, act, l8+6);

        c = fmaf(fg, c, ig*gg);
        float h = og * tanhf_fast(c);
        if ((tid & 7) == 0) {
            hbuf[cur^1][hh] = h;
            hstage[(t>>4)&1][hh][t & 15] = h;
        }

        // next-step x contribution (off critical path)
        int tn = (t + 1) & (SEQ - 1);
        const float* xt = xs + tn*INP;
        float xn = bias;
        #pragma unroll
        for (int i = 0; i < INP; ++i) xn = fmaf(xt[i], wih[i], xn);
        xacc = xn;

        __syncthreads();
        cur ^= 1;

        if ((t & 15) == 15 && tid < 256) {
            int wsel = (t >> 4) & 1;
            int k = tid >> 2;
            int j = (tid & 3) * 4;
            const float* hp = &hstage[wsel][k][j];
            float4 v = make_float4(hp[0], hp[1], hp[2], hp[3]);
            *(float4*)(g_hT + (size_t)k*MTOT + (size_t)b*SEQ + (t-15) + j) = v;
        }
    }
}

// ---------------------------------------------------------------------------
// FC on tensor cores (round-10 proven version, verbatim): tf32 MMA,
// CTA 256 thr / 8 warps, tile 128m x 64n, MLOOP=8, A register-prefetched.
// ---------------------------------------------------------------------------
#define AST   136
#define MLOOP 8

__global__ __launch_bounds__(256, 1)
void fc_mma_kernel(const float* __restrict__ W_fc,
                   const float* __restrict__ b_fc,
                   float* __restrict__ out)
{
    extern __shared__ u32 smemu[];
    u32*   As  = smemu;                        // [64][AST] tf32 bits, 34816 B
    uint4* Bs4 = (uint4*)(smemu + HID*AST);    // [8][4][32] fragments, 16384 B

    const int tid  = threadIdx.x;
    const int lane = tid & 31;
    const int warp = tid >> 5;
    const int lg   = lane >> 2;
    const int lt   = lane & 3;
    const int col0 = blockIdx.y * 64;
    const int ROW0 = blockIdx.x * (128 * MLOOP);

    #pragma unroll
    for (int q = 0; q < 4; ++q) {
        int idx = tid + q*256;
        int bl  = idx & 31;
        int jj  = (idx >> 5) & 3;
        int s   = idx >> 7;
        int kA  = s*8 + (bl & 3);
        int n1  = col0 + jj*16 + (bl >> 2);
        int n2  = n1 + 8;
        float fx=0.f, fy=0.f, fz=0.f, fw=0.f;
        if (n1 < OUTD) { fx = W_fc[n1*HID + kA]; fy = W_fc[n1*HID + kA + 4]; }
        if (n2 < OUTD) { fz = W_fc[n2*HID + kA]; fw = W_fc[n2*HID + kA + 4]; }
        Bs4[(s*4 + jj)*32 + bl] =
            make_uint4(cvt_tf32(fx), cvt_tf32(fy), cvt_tf32(fz), cvt_tf32(fw));
    }

    float2 biasj[8];
    #pragma unroll
    for (int j = 0; j < 8; ++j) {
        int nj = col0 + j*8 + lt*2;
        if (nj < OUTD) { biasj[j].x = b_fc[nj]; biasj[j].y = b_fc[nj+1]; }
        else           { biasj[j].x = 0.f;      biasj[j].y = 0.f; }
    }

    int ak[8];
    #pragma unroll
    for (int l = 0; l < 8; ++l) ak[l] = (tid + l*256) >> 5;
    const int am = (tid & 31) * 4;

    float4 pre[8];
    #pragma unroll
    for (int l = 0; l < 8; ++l)
        pre[l] = *(const float4*)(g_hT + (size_t)ak[l]*MTOT + ROW0 + am);

    for (int mt = 0; mt < MLOOP; ++mt) {
        __syncthreads();
        #pragma unroll
        for (int l = 0; l < 8; ++l) {
            uint4 v = make_uint4(cvt_tf32(pre[l].x), cvt_tf32(pre[l].y),
                                 cvt_tf32(pre[l].z), cvt_tf32(pre[l].w));
            *(uint4*)&As[ak[l]*AST + am] = v;
        }
        __syncthreads();

        if (mt + 1 < MLOOP) {
            const int rn = ROW0 + (mt+1)*128;
            #pragma unroll
            for (int l = 0; l < 8; ++l)
                pre[l] = *(const float4*)(g_hT + (size_t)ak[l]*MTOT + rn + am);
        }

        float d[8][4];
        #pragma unroll
        for (int j = 0; j < 8; ++j)
            #pragma unroll
            for (int p = 0; p < 4; ++p) d[j][p] = 0.f;

        #pragma unroll
        for (int s = 0; s < 8; ++s) {
            const int ka = s*8 + lt;
            const int mb = 16*warp + lg;
            u32 a0 = As[ ka      *AST + mb    ];
            u32 a1 = As[ ka      *AST + mb + 8];
            u32 a2 = As[(ka + 4) *AST + mb    ];
            u32 a3 = As[(ka + 4) *AST + mb + 8];
            #pragma unroll
            for (int jj = 0; jj < 4; ++jj) {
                uint4 bb = Bs4[(s*4 + jj)*32 + lane];
                mma_tf32(d[2*jj  ], a0, a1, a2, a3, bb.x, bb.y);
                mma_tf32(d[2*jj+1], a0, a1, a2, a3, bb.z, bb.w);
            }
        }

        const int r0 = ROW0 + mt*128 + 16*warp + lg;
        float* o0 = out + (size_t)r0 * OUTD;
        float* o1 = o0 + 8 * OUTD;
        #pragma unroll
        for (int j = 0; j < 8; ++j) {
            int nj = col0 + j*8 + lt*2;
            if (nj < OUTD) {
                float2 v0, v1;
                v0.x = d[j][0] + biasj[j].x;  v0.y = d[j][1] + biasj[j].y;
                v1.x = d[j][2] + biasj[j].x;  v1.y = d[j][3] + biasj[j].y;
                *(float2*)(o0 + nj) = v0;
                *(float2*)(o1 + nj) = v1;
            }
        }
    }
}

extern "C" void kernel_launch(void* const* d_in, const int* in_sizes, int n_in,
                              void* d_out, int out_size)
{
    const float* x    = (const float*)d_in[0];
    const float* W_ih = (const float*)d_in[1];
    const float* W_hh = (const float*)d_in[2];
    const float* b_ih = (const float*)d_in[3];
    const float* b_hh = (const float*)d_in[4];
    const float* W_fc = (const float*)d_in[5];
    const float* b_fc = (const float*)d_in[6];
    float* out = (float*)d_out;

    static int smem_set = 0;
    const int dyn = (HID*AST*4) + (8*4*32*16);   // 51200 B
    if (!smem_set) {
        cudaFuncSetAttribute(fc_mma_kernel,
                             cudaFuncAttributeMaxDynamicSharedMemorySize, dyn);
        smem_set = 1;
    }
    lstm_kernel<<<BATCH, 512>>>(x, W_ih, W_hh, b_ih, b_hh);
    fc_mma_kernel<<<dim3(MTOT/(128*MLOOP), 8), 256, dyn>>>(W_fc, b_fc, out);
}

// round 13
// speedup vs baseline: 1.1594x; 1.1594x over previous
#include <cuda_runtime.h>
#include <math.h>

#define BATCH 128
#define SEQ   1024
#define INP   7
#define HID   64
#define OUTD  500
#define MTOT  (BATCH*SEQ)   // 131072
#define HSP   20
#define NLSTM 128
#define GRID  256
#define AST   136           // fc A smem row stride (u32): conflict-free

typedef unsigned long long u64;
typedef unsigned int u32;

__device__ float g_hT[(size_t)HID * MTOT];   // h transposed: g_hT[k][b*SEQ+t]
__device__ volatile int g_prog[BATCH];       // lstm progress per batch

// ---- f32x2 packed helpers (lstm) ----
__device__ __forceinline__ u64 ffma2(u64 a, u64 b, u64 c) {
    u64 d;
    asm("fma.rn.f32x2 %0, %1, %2, %3;" : "=l"(d) : "l"(a), "l"(b), "l"(c));
    return d;
}
__device__ __forceinline__ u64 fadd2(u64 a, u64 b) {
    u64 d;
    asm("add.rn.f32x2 %0, %1, %2;" : "=l"(d) : "l"(a), "l"(b));
    return d;
}
__device__ __forceinline__ void unpack2(u64 v, float& lo, float& hi) {
    u32 l, h;
    asm("mov.b64 {%0, %1}, %2;" : "=r"(l), "=r"(h) : "l"(v));
    lo = __uint_as_float(l); hi = __uint_as_float(h);
}
__device__ __forceinline__ float tanhf_fast(float x) {
    float y;
    asm("tanh.approx.f32 %0, %1;" : "=f"(y) : "f"(x));
    return y;
}
// ---- tf32 helpers (fc) ----
__device__ __forceinline__ u32 cvt_tf32(float x) {
    u32 r; asm("cvt.rna.tf32.f32 %0, %1;" : "=r"(r) : "f"(x)); return r;
}
__device__ __forceinline__ void mma_tf32(float* d,
    u32 a0, u32 a1, u32 a2, u32 a3, u32 b0, u32 b1)
{
    asm volatile(
        "mma.sync.aligned.m16n8k8.row.col.f32.tf32.tf32.f32 "
        "{%0,%1,%2,%3}, {%4,%5,%6,%7}, {%8,%9}, {%0,%1,%2,%3};"
        : "+f"(d[0]), "+f"(d[1]), "+f"(d[2]), "+f"(d[3])
        : "r"(a0), "r"(a1), "r"(a2), "r"(a3), "r"(b0), "r"(b1));
}

// ---------------------------------------------------------------------------
// LSTM role (proven R3/R10 core + progress flags): one CTA per batch, 256 thr.
// ---------------------------------------------------------------------------
__device__ void lstm_role(char* dynsmem, int b,
                          const float* __restrict__ x,
                          const float* __restrict__ W_ih,
                          const float* __restrict__ W_hh,
                          const float* __restrict__ b_ih,
                          const float* __restrict__ b_hh)
{
    float* xs     = (float*)dynsmem;            // [SEQ*INP]       28672 B
    float* hbuf   = xs + SEQ*INP;               // [2][HID]          512 B
    float* hstage = hbuf + 2*HID;               // [2][HID][HSP]   10240 B

    const int tid  = threadIdx.x;
    const int hh   = tid >> 2;
    const int gate = tid & 3;
    const int row  = gate * HID + hh;
    const int lane = tid & 31;
    const int lb   = lane & ~3;

    {
        const float4* src = (const float4*)(x + (size_t)b * SEQ * INP);
        float4* dst = (float4*)xs;
        #pragma unroll
        for (int i = 0; i < (SEQ*INP)/(4*256); ++i)
            dst[tid + i*256] = src[tid + i*256];
    }

    u64 w2[HID/2];
    {
        const ulonglong2* wr = (const ulonglong2*)(W_hh + (size_t)row * HID);
        #pragma unroll
        for (int i = 0; i < HID/4; ++i) {
            ulonglong2 v = wr[i];
            w2[2*i+0] = v.x; w2[2*i+1] = v.y;
        }
    }
    float wih[INP];
    #pragma unroll
    for (int i = 0; i < INP; ++i) wih[i] = W_ih[row*INP + i];
    const float bias = b_ih[row] + b_hh[row];

    const float scale = (gate == 2) ? 1.0f : 0.5f;
    const float off   = (gate == 2) ? 0.0f : 0.5f;

    if (tid < HID) hbuf[tid] = 0.0f;
    float c = 0.0f;
    __syncthreads();

    float xacc = bias;
    #pragma unroll
    for (int i = 0; i < INP; ++i) xacc = fmaf(xs[i], wih[i], xacc);

    int cur = 0;
    for (int t = 0; t < SEQ; ++t) {
        const ulonglong2* hv = (const ulonglong2*)(hbuf + cur*HID);
        u64 a[8];
        #pragma unroll
        for (int i = 0; i < 8; ++i) a[i] = 0ull;
        #pragma unroll
        for (int j = 0; j < 4; ++j) {
            ulonglong2 h0 = hv[4*j+0];
            ulonglong2 h1 = hv[4*j+1];
            ulonglong2 h2 = hv[4*j+2];
            ulonglong2 h3 = hv[4*j+3];
            a[0] = ffma2(h0.x, w2[8*j+0], a[0]);
            a[1] = ffma2(h0.y, w2[8*j+1], a[1]);
            a[2] = ffma2(h1.x, w2[8*j+2], a[2]);
            a[3] = ffma2(h1.y, w2[8*j+3], a[3]);
            a[4] = ffma2(h2.x, w2[8*j+4], a[4]);
            a[5] = ffma2(h2.y, w2[8*j+5], a[5]);
            a[6] = ffma2(h3.x, w2[8*j+6], a[6]);
            a[7] = ffma2(h3.y, w2[8*j+7], a[7]);
        }
        u64 s0 = fadd2(a[0], a[1]);
        u64 s1 = fadd2(a[2], a[3]);
        u64 s2 = fadd2(a[4], a[5]);
        u64 s3 = fadd2(a[6], a[7]);
        u64 s  = fadd2(fadd2(s0, s1), fadd2(s2, s3));
        float slo, shi; unpack2(s, slo, shi);
        float pre = xacc + slo + shi;

        float act = fmaf(scale, tanhf_fast(scale * pre), off);

        float ig = __shfl_sync(0xffffffffu, act, lb+0);
        float fg = __shfl_sync(0xffffffffu, act, lb+1);
        float gg = __shfl_sync(0xffffffffu, act, lb+2);
        float og = __shfl_sync(0xffffffffu, act, lb+3);

        c = fmaf(fg, c, ig*gg);
        float h = og * tanhf_fast(c);
        if (gate == 0) {
            hbuf[(cur^1)*HID + hh] = h;
            hstage[(((t>>4)&1)*HID + hh)*HSP + (t & 15)] = h;
        }

        int tn = (t + 1) & (SEQ - 1);
        const float* xt = xs + tn*INP;
        float xn = bias;
        #pragma unroll
        for (int i = 0; i < INP; ++i) xn = fmaf(xt[i], wih[i], xn);
        xacc = xn;

        __syncthreads();
        cur ^= 1;

        if ((t & 15) == 15) {
            int wsel = (t >> 4) & 1;
            int k = tid >> 2;
            int j = (tid & 3) * 4;
            const float* hp = &hstage[(wsel*HID + k)*HSP + j];
            float4 v = make_float4(hp[0], hp[1], hp[2], hp[3]);
            *(float4*)(g_hT + (size_t)k*MTOT + (size_t)b*SEQ + (t-15) + j) = v;
            __threadfence();   // order dump before the next flag publish
        } else if ((t & 15) == 0 && t != 0) {
            if (tid == 0) g_prog[b] = t;   // prev window's dumps+fences ordered
        }
    }
    __syncthreads();
    if (tid == 0) g_prog[b] = SEQ;
}

// ---------------------------------------------------------------------------
// FC role (tensor-core tf32): one CTA per batch, consumes 128-row windows as
// they publish. Per window: stage A once, then 8 n-tiles of 64 cols
// (B fragments restaged from L2-resident W_fc each tile).
// ---------------------------------------------------------------------------
__device__ void fc_role(char* dynsmem, int b,
                        const float* __restrict__ W_fc,
                        const float* __restrict__ b_fc,
                        float* __restrict__ out)
{
    u32*   As  = (u32*)dynsmem;                          // [64][AST]  34816 B
    uint4* Bs4 = (uint4*)(dynsmem + HID*AST*4);          // [8][4][32] 16384 B

    const int tid  = threadIdx.x;
    const int lane = tid & 31;
    const int warp = tid >> 5;
    const int lg   = lane >> 2;
    const int lt   = lane & 3;

    for (int w = 0; w < 8; ++w) {
        if (tid == 0) {
            while (g_prog[b] < (w + 1) * 128) { __nanosleep(256); }
            __threadfence();                 // acquire
        }
        __syncthreads();                     // all prev-window reads done too

        const int rowbase = b * SEQ + w * 128;

        // ---- stage A for this window (once) ----
        #pragma unroll
        for (int l = 0; l < 8; ++l) {
            int fid = tid + l*256;
            int k   = fid >> 5;
            int m4  = (fid & 31) * 4;
            float4 v = *(const float4*)(g_hT + (size_t)k*MTOT + rowbase + m4);
            *(uint4*)&As[k*AST + m4] =
                make_uint4(cvt_tf32(v.x), cvt_tf32(v.y),
                           cvt_tf32(v.z), cvt_tf32(v.w));
        }

        for (int nt = 0; nt < 8; ++nt) {
            const int col0 = nt * 64;
            __syncthreads();   // prev tile's MMA reads done (A visible on nt=0)
            // ---- stage B fragments for this 64-col tile ----
            #pragma unroll
            for (int q = 0; q < 4; ++q) {
                int idx = tid + q*256;
                int bl  = idx & 31;
                int jj  = (idx >> 5) & 3;
                int s   = idx >> 7;
                int kA  = s*8 + (bl & 3);
                int n1  = col0 + jj*16 + (bl >> 2);
                int n2  = n1 + 8;
                float fx=0.f, fy=0.f, fz=0.f, fw=0.f;
                if (n1 < OUTD) { fx = W_fc[n1*HID + kA]; fy = W_fc[n1*HID + kA + 4]; }
                if (n2 < OUTD) { fz = W_fc[n2*HID + kA]; fw = W_fc[n2*HID + kA + 4]; }
                Bs4[(s*4 + jj)*32 + bl] =
                    make_uint4(cvt_tf32(fx), cvt_tf32(fy), cvt_tf32(fz), cvt_tf32(fw));
            }
            __syncthreads();

            float d[8][4];
            #pragma unroll
            for (int j = 0; j < 8; ++j)
                #pragma unroll
                for (int p = 0; p < 4; ++p) d[j][p] = 0.f;

            #pragma unroll
            for (int s = 0; s < 8; ++s) {
                const int ka = s*8 + lt;
                const int mb = 16*warp + lg;
                u32 a0 = As[ ka      *AST + mb    ];
                u32 a1 = As[ ka      *AST + mb + 8];
                u32 a2 = As[(ka + 4) *AST + mb    ];
                u32 a3 = As[(ka + 4) *AST + mb + 8];
                #pragma unroll
                for (int jj = 0; jj < 4; ++jj) {
                    uint4 bb = Bs4[(s*4 + jj)*32 + lane];
                    mma_tf32(d[2*jj  ], a0, a1, a2, a3, bb.x, bb.y);
                    mma_tf32(d[2*jj+1], a0, a1, a2, a3, bb.z, bb.w);
                }
            }

            const int r0 = rowbase + 16*warp + lg;
            float* o0 = out + (size_t)r0 * OUTD;
            float* o1 = o0 + 8 * OUTD;
            #pragma unroll
            for (int j = 0; j < 8; ++j) {
                int nj = col0 + j*8 + lt*2;
                if (nj < OUTD) {
                    float bx = b_fc[nj], by = b_fc[nj+1];
                    float2 v0, v1;
                    v0.x = d[j][0] + bx;  v0.y = d[j][1] + by;
                    v1.x = d[j][2] + bx;  v1.y = d[j][3] + by;
                    *(float2*)(o0 + nj) = v0;
                    *(float2*)(o1 + nj) = v1;
                }
            }
        }
    }
}

// ---------------------------------------------------------------------------
// Fused kernel: blocks 0..127 lstm, 128..255 fc (batch = bid-128).
// 2 CTAs/SM (regs<=128, smem 51.2KB x2); classic placement guarantees no SM
// hosts two lstm CTAs; all 256 CTAs resident in wave 1 (no deadlock).
// ---------------------------------------------------------------------------
__global__ __launch_bounds__(256, 2)
void fused_kernel(const float* __restrict__ x,
                  const float* __restrict__ W_ih,
                  const float* __restrict__ W_hh,
                  const float* __restrict__ b_ih,
                  const float* __restrict__ b_hh,
                  const float* __restrict__ W_fc,
                  const float* __restrict__ b_fc,
                  float* __restrict__ out)
{
    extern __shared__ char dynsmem[];
    const int bid = blockIdx.x;
    if (bid < NLSTM) lstm_role(dynsmem, bid, x, W_ih, W_hh, b_ih, b_hh);
    else             fc_role(dynsmem, bid - NLSTM, W_fc, b_fc, out);
}

__global__ void reset_kernel()
{
    int i = threadIdx.x;
    if (i < BATCH) g_prog[i] = 0;
}

extern "C" void kernel_launch(void* const* d_in, const int* in_sizes, int n_in,
                              void* d_out, int out_size)
{
    const float* x    = (const float*)d_in[0];
    const float* W_ih = (const float*)d_in[1];
    const float* W_hh = (const float*)d_in[2];
    const float* b_ih = (const float*)d_in[3];
    const float* b_hh = (const float*)d_in[4];
    const float* W_fc = (const float*)d_in[5];
    const float* b_fc = (const float*)d_in[6];
    float* out = (float*)d_out;

    static int smem_set = 0;
    const int dyn = (HID*AST*4) + (8*4*32*16);   // 51200 B (fc); lstm uses 39.4K
    if (!smem_set) {
        cudaFuncSetAttribute(fused_kernel,
                             cudaFuncAttributeMaxDynamicSharedMemorySize, dyn);
        smem_set = 1;
    }
    reset_kernel<<<1, 128>>>();
    fused_kernel<<<GRID, 256, dyn>>>(x, W_ih, W_hh, b_ih, b_hh, W_fc, b_fc, out);
}

// round 14
// speedup vs baseline: 1.3025x; 1.1235x over previous
#include <cuda_runtime.h>
#include <math.h>

#define BATCH 128
#define SEQ   1024
#define INP   7
#define HID   64
#define OUTD  500
#define MTOT  (BATCH*SEQ)   // 131072
#define HSP   20

typedef unsigned long long u64;
typedef unsigned int u32;

__device__ float g_hT[(size_t)HID * MTOT];   // h transposed: g_hT[k][b*SEQ+t]

// ---- f32x2 packed helpers (lstm) ----
__device__ __forceinline__ u64 ffma2(u64 a, u64 b, u64 c) {
    u64 d;
    asm("fma.rn.f32x2 %0, %1, %2, %3;" : "=l"(d) : "l"(a), "l"(b), "l"(c));
    return d;
}
__device__ __forceinline__ u64 fadd2(u64 a, u64 b) {
    u64 d;
    asm("add.rn.f32x2 %0, %1, %2;" : "=l"(d) : "l"(a), "l"(b));
    return d;
}
__device__ __forceinline__ void unpack2(u64 v, float& lo, float& hi) {
    u32 l, h;
    asm("mov.b64 {%0, %1}, %2;" : "=r"(l), "=r"(h) : "l"(v));
    lo = __uint_as_float(l); hi = __uint_as_float(h);
}
__device__ __forceinline__ float tanhf_fast(float x) {
    float y;
    asm("tanh.approx.f32 %0, %1;" : "=f"(y) : "f"(x));
    return y;
}
// ---- tf32 / cp.async helpers (fc) ----
__device__ __forceinline__ u32 cvt_tf32(float x) {
    u32 r; asm("cvt.rna.tf32.f32 %0, %1;" : "=r"(r) : "f"(x)); return r;
}
__device__ __forceinline__ void mma_tf32(float* d,
    u32 a0, u32 a1, u32 a2, u32 a3, u32 b0, u32 b1)
{
    asm volatile(
        "mma.sync.aligned.m16n8k8.row.col.f32.tf32.tf32.f32 "
        "{%0,%1,%2,%3}, {%4,%5,%6,%7}, {%8,%9}, {%0,%1,%2,%3};"
        : "+f"(d[0]), "+f"(d[1]), "+f"(d[2]), "+f"(d[3])
        : "r"(a0), "r"(a1), "r"(a2), "r"(a3), "r"(b0), "r"(b1));
}
__device__ __forceinline__ void cp_async16(u32 saddr, const void* gptr) {
    asm volatile("cp.async.cg.shared.global [%0], [%1], 16;"
                 :: "r"(saddr), "l"(gptr));
}
#define CP_COMMIT() asm volatile("cp.async.commit_group;" ::: "memory")
#define CP_WAIT0()  asm volatile("cp.async.wait_group 0;"  ::: "memory")

// ---------------------------------------------------------------------------
// LSTM recurrence (proven R10 core, verbatim): one CTA per batch, 256 threads.
// ---------------------------------------------------------------------------
__global__ __launch_bounds__(256, 1)
void lstm_kernel(const float* __restrict__ x,
                 const float* __restrict__ W_ih,
                 const float* __restrict__ W_hh,
                 const float* __restrict__ b_ih,
                 const float* __restrict__ b_hh)
{
    __shared__ float xs[SEQ * INP];                      // 28 KB
    __shared__ __align__(16) float hbuf[2][HID];
    __shared__ __align__(16) float hstage[2][HID][HSP];  // 10 KB

    const int b    = blockIdx.x;
    const int tid  = threadIdx.x;
    const int hh   = tid >> 2;
    const int gate = tid & 3;
    const int row  = gate * HID + hh;
    const int lane = tid & 31;
    const int lb   = lane & ~3;

    {
        const float4* src = (const float4*)(x + (size_t)b * SEQ * INP);
        float4* dst = (float4*)xs;
        #pragma unroll
        for (int i = 0; i < (SEQ*INP)/(4*256); ++i)
            dst[tid + i*256] = src[tid + i*256];
    }

    u64 w2[HID/2];
    {
        const ulonglong2* wr = (const ulonglong2*)(W_hh + (size_t)row * HID);
        #pragma unroll
        for (int i = 0; i < HID/4; ++i) {
            ulonglong2 v = wr[i];
            w2[2*i+0] = v.x; w2[2*i+1] = v.y;
        }
    }
    float wih[INP];
    #pragma unroll
    for (int i = 0; i < INP; ++i) wih[i] = W_ih[row*INP + i];
    const float bias = b_ih[row] + b_hh[row];

    const float scale = (gate == 2) ? 1.0f : 0.5f;
    const float off   = (gate == 2) ? 0.0f : 0.5f;

    if (tid < HID) hbuf[0][tid] = 0.0f;
    float c = 0.0f;
    __syncthreads();

    float xacc = bias;
    #pragma unroll
    for (int i = 0; i < INP; ++i) xacc = fmaf(xs[i], wih[i], xacc);

    int cur = 0;
    for (int t = 0; t < SEQ; ++t) {
        const ulonglong2* hv = (const ulonglong2*)hbuf[cur];
        u64 a[8];
        #pragma unroll
        for (int i = 0; i < 8; ++i) a[i] = 0ull;
        #pragma unroll
        for (int j = 0; j < 4; ++j) {
            ulonglong2 h0 = hv[4*j+0];
            ulonglong2 h1 = hv[4*j+1];
            ulonglong2 h2 = hv[4*j+2];
            ulonglong2 h3 = hv[4*j+3];
            a[0] = ffma2(h0.x, w2[8*j+0], a[0]);
            a[1] = ffma2(h0.y, w2[8*j+1], a[1]);
            a[2] = ffma2(h1.x, w2[8*j+2], a[2]);
            a[3] = ffma2(h1.y, w2[8*j+3], a[3]);
            a[4] = ffma2(h2.x, w2[8*j+4], a[4]);
            a[5] = ffma2(h2.y, w2[8*j+5], a[5]);
            a[6] = ffma2(h3.x, w2[8*j+6], a[6]);
            a[7] = ffma2(h3.y, w2[8*j+7], a[7]);
        }
        u64 s0 = fadd2(a[0], a[1]);
        u64 s1 = fadd2(a[2], a[3]);
        u64 s2 = fadd2(a[4], a[5]);
        u64 s3 = fadd2(a[6], a[7]);
        u64 s  = fadd2(fadd2(s0, s1), fadd2(s2, s3));
        float slo, shi; unpack2(s, slo, shi);
        float pre = xacc + slo + shi;

        float act = fmaf(scale, tanhf_fast(scale * pre), off);

        float ig = __shfl_sync(0xffffffffu, act, lb+0);
        float fg = __shfl_sync(0xffffffffu, act, lb+1);
        float gg = __shfl_sync(0xffffffffu, act, lb+2);
        float og = __shfl_sync(0xffffffffu, act, lb+3);

        c = fmaf(fg, c, ig*gg);
        float h = og * tanhf_fast(c);
        if (gate == 0) {
            hbuf[cur^1][hh] = h;
            hstage[(t>>4)&1][hh][t & 15] = h;
        }

        int tn = (t + 1) & (SEQ - 1);
        const float* xt = xs + tn*INP;
        float xn = bias;
        #pragma unroll
        for (int i = 0; i < INP; ++i) xn = fmaf(xt[i], wih[i], xn);
        xacc = xn;

        __syncthreads();
        cur ^= 1;

        if ((t & 15) == 15) {
            int wsel = (t >> 4) & 1;
            int k = tid >> 2;
            int j = (tid & 3) * 4;
            const float* hp = &hstage[wsel][k][j];
            float4 v = make_float4(hp[0], hp[1], hp[2], hp[3]);
            *(float4*)(g_hT + (size_t)k*MTOT + (size_t)b*SEQ + (t-15) + j) = v;
        }
    }
}

// ---------------------------------------------------------------------------
// FC on tensor cores (tf32 MMA): cp.async double-buffered A staging, raw-fp32
// A operands (HW tf32 truncation), 2 CTAs/SM. Tile 128m x 64n, MLOOP=8.
// ---------------------------------------------------------------------------
#define AST   136      // A smem row stride (u32): conflict-free, 16B-aligned
#define MLOOP 8

__global__ __launch_bounds__(256, 2)
void fc_mma_kernel(const float* __restrict__ W_fc,
                   const float* __restrict__ b_fc,
                   float* __restrict__ out)
{
    extern __shared__ u32 smemu[];
    u32*   Abuf[2] = { smemu, smemu + HID*AST };        // 2 x 34816 B
    uint4* Bs4 = (uint4*)(smemu + 2*HID*AST);           // [8][4][32] 16384 B
    float* bs  = (float*)(Bs4 + 8*4*32);                // [64] bias

    const int tid  = threadIdx.x;
    const int lane = tid & 31;
    const int warp = tid >> 5;
    const int lg   = lane >> 2;
    const int lt   = lane & 3;
    const int col0 = blockIdx.y * 64;
    const int ROW0 = blockIdx.x * (128 * MLOOP);

    // ---- stage B fragments + bias (once per CTA, rna-rounded) ----
    #pragma unroll
    for (int q = 0; q < 4; ++q) {
        int idx = tid + q*256;
        int bl  = idx & 31;
        int jj  = (idx >> 5) & 3;
        int s   = idx >> 7;
        int kA  = s*8 + (bl & 3);
        int n1  = col0 + jj*16 + (bl >> 2);
        int n2  = n1 + 8;
        float fx=0.f, fy=0.f, fz=0.f, fw=0.f;
        if (n1 < OUTD) { fx = W_fc[n1*HID + kA]; fy = W_fc[n1*HID + kA + 4]; }
        if (n2 < OUTD) { fz = W_fc[n2*HID + kA]; fw = W_fc[n2*HID + kA + 4]; }
        Bs4[(s*4 + jj)*32 + bl] =
            make_uint4(cvt_tf32(fx), cvt_tf32(fy), cvt_tf32(fz), cvt_tf32(fw));
    }
    if (tid < 64) {
        int n = col0 + tid;
        bs[tid] = (n < OUTD) ? b_fc[n] : 0.0f;
    }

    // A gather indices (thread-invariant)
    int ak[8];
    #pragma unroll
    for (int l = 0; l < 8; ++l) ak[l] = (tid + l*256) >> 5;
    const int am = (tid & 31) * 4;

    // issue cp.async for mt=0 into buffer 0
    {
        u32 sbase = (u32)__cvta_generic_to_shared(Abuf[0]);
        #pragma unroll
        for (int l = 0; l < 8; ++l)
            cp_async16(sbase + (u32)(ak[l]*AST + am)*4,
                       g_hT + (size_t)ak[l]*MTOT + ROW0 + am);
        CP_COMMIT();
    }

    for (int mt = 0; mt < MLOOP; ++mt) {
        u32* Acur = Abuf[mt & 1];
        u32* Anxt = Abuf[(mt & 1) ^ 1];

        CP_WAIT0();
        __syncthreads();   // A(mt) ready; all reads of Anxt's buffer finished

        if (mt + 1 < MLOOP) {
            u32 sbase = (u32)__cvta_generic_to_shared(Anxt);
            const int rn = ROW0 + (mt+1)*128;
            #pragma unroll
            for (int l = 0; l < 8; ++l)
                cp_async16(sbase + (u32)(ak[l]*AST + am)*4,
                           g_hT + (size_t)ak[l]*MTOT + rn + am);
            CP_COMMIT();
        }

        float d[8][4];
        #pragma unroll
        for (int j = 0; j < 8; ++j)
            #pragma unroll
            for (int p = 0; p < 4; ++p) d[j][p] = 0.f;

        #pragma unroll
        for (int s = 0; s < 8; ++s) {
            const int ka = s*8 + lt;
            const int mb = 16*warp + lg;
            // raw fp32 bits as tf32 operands (HW truncates mantissa)
            u32 a0 = Acur[ ka      *AST + mb    ];
            u32 a1 = Acur[ ka      *AST + mb + 8];
            u32 a2 = Acur[(ka + 4) *AST + mb    ];
            u32 a3 = Acur[(ka + 4) *AST + mb + 8];
            #pragma unroll
            for (int jj = 0; jj < 4; ++jj) {
                uint4 bb = Bs4[(s*4 + jj)*32 + lane];
                mma_tf32(d[2*jj  ], a0, a1, a2, a3, bb.x, bb.y);
                mma_tf32(d[2*jj+1], a0, a1, a2, a3, bb.z, bb.w);
            }
        }

        const int r0 = ROW0 + mt*128 + 16*warp + lg;
        float* o0 = out + (size_t)r0 * OUTD;
        float* o1 = o0 + 8 * OUTD;
        #pragma unroll
        for (int j = 0; j < 8; ++j) {
            int njl = j*8 + lt*2;
            int nj  = col0 + njl;
            if (nj < OUTD) {
                float bx = bs[njl], by = bs[njl+1];
                float2 v0, v1;
                v0.x = d[j][0] + bx;  v0.y = d[j][1] + by;
                v1.x = d[j][2] + bx;  v1.y = d[j][3] + by;
                *(float2*)(o0 + nj) = v0;
                *(float2*)(o1 + nj) = v1;
            }
        }
        __syncthreads();   // all reads of Acur done before it's refilled
    }
}

extern "C" void kernel_launch(void* const* d_in, const int* in_sizes, int n_in,
                              void* d_out, int out_size)
{
    const float* x    = (const float*)d_in[0];
    const float* W_ih = (const float*)d_in[1];
    const float* W_hh = (const float*)d_in[2];
    const float* b_ih = (const float*)d_in[3];
    const float* b_hh = (const float*)d_in[4];
    const float* W_fc = (const float*)d_in[5];
    const float* b_fc = (const float*)d_in[6];
    float* out = (float*)d_out;

    static int smem_set = 0;
    const int dyn = 2*(HID*AST*4) + (8*4*32*16) + 256;   // 69632+16384+256 = 86272
    if (!smem_set) {
        cudaFuncSetAttribute(fc_mma_kernel,
                             cudaFuncAttributeMaxDynamicSharedMemorySize, dyn);
        smem_set = 1;
    }
    lstm_kernel<<<BATCH, 256>>>(x, W_ih, W_hh, b_ih, b_hh);
    fc_mma_kernel<<<dim3(MTOT/(128*MLOOP), 8), 256, dyn>>>(W_fc, b_fc, out);
}

// round 15
// speedup vs baseline: 1.4308x; 1.0985x over previous
#include <cuda_runtime.h>
#include <math.h>

#define BATCH 128
#define SEQ   1024
#define INP   7
#define HID   64
#define OUTD  500
#define MTOT  (BATCH*SEQ)   // 131072
#define HSP   20

typedef unsigned long long u64;
typedef unsigned int u32;

__device__ float g_hT[(size_t)HID * MTOT];   // h transposed: g_hT[k][b*SEQ+t]

// ---- f32x2 packed helpers (lstm) ----
__device__ __forceinline__ u64 ffma2(u64 a, u64 b, u64 c) {
    u64 d;
    asm("fma.rn.f32x2 %0, %1, %2, %3;" : "=l"(d) : "l"(a), "l"(b), "l"(c));
    return d;
}
__device__ __forceinline__ u64 fadd2(u64 a, u64 b) {
    u64 d;
    asm("add.rn.f32x2 %0, %1, %2;" : "=l"(d) : "l"(a), "l"(b));
    return d;
}
__device__ __forceinline__ void unpack2(u64 v, float& lo, float& hi) {
    u32 l, h;
    asm("mov.b64 {%0, %1}, %2;" : "=r"(l), "=r"(h) : "l"(v));
    lo = __uint_as_float(l); hi = __uint_as_float(h);
}
__device__ __forceinline__ float tanhf_fast(float x) {
    float y;
    asm("tanh.approx.f32 %0, %1;" : "=f"(y) : "f"(x));
    return y;
}
// ---- tf32 / cp.async helpers (fc) ----
__device__ __forceinline__ u32 cvt_tf32(float x) {
    u32 r; asm("cvt.rna.tf32.f32 %0, %1;" : "=r"(r) : "f"(x)); return r;
}
__device__ __forceinline__ void mma_tf32(float* d,
    u32 a0, u32 a1, u32 a2, u32 a3, u32 b0, u32 b1)
{
    asm volatile(
        "mma.sync.aligned.m16n8k8.row.col.f32.tf32.tf32.f32 "
        "{%0,%1,%2,%3}, {%4,%5,%6,%7}, {%8,%9}, {%0,%1,%2,%3};"
        : "+f"(d[0]), "+f"(d[1]), "+f"(d[2]), "+f"(d[3])
        : "r"(a0), "r"(a1), "r"(a2), "r"(a3), "r"(b0), "r"(b1));
}
__device__ __forceinline__ void cp_async16(u32 saddr, const void* gptr) {
    asm volatile("cp.async.cg.shared.global [%0], [%1], 16;"
                 :: "r"(saddr), "l"(gptr));
}
#define CP_COMMIT() asm volatile("cp.async.commit_group;" ::: "memory")
#define CP_WAIT0()  asm volatile("cp.async.wait_group 0;"  ::: "memory")

// ---------------------------------------------------------------------------
// LSTM recurrence: R10 core with ONE change — the x-contribution (xacc) is
// computed at the TOP of each iteration (overlapping the h.W dot-product
// latency) instead of between the h-store and the barrier, where its
// LDS+serial-FMA chain (~60 cyc) delayed every warp's barrier arrival.
// ---------------------------------------------------------------------------
__global__ __launch_bounds__(256, 1)
void lstm_kernel(const float* __restrict__ x,
                 const float* __restrict__ W_ih,
                 const float* __restrict__ W_hh,
                 const float* __restrict__ b_ih,
                 const float* __restrict__ b_hh)
{
    __shared__ float xs[SEQ * INP];                      // 28 KB
    __shared__ __align__(16) float hbuf[2][HID];
    __shared__ __align__(16) float hstage[2][HID][HSP];  // 10 KB

    const int b    = blockIdx.x;
    const int tid  = threadIdx.x;
    const int hh   = tid >> 2;
    const int gate = tid & 3;
    const int row  = gate * HID + hh;
    const int lane = tid & 31;
    const int lb   = lane & ~3;

    {
        const float4* src = (const float4*)(x + (size_t)b * SEQ * INP);
        float4* dst = (float4*)xs;
        #pragma unroll
        for (int i = 0; i < (SEQ*INP)/(4*256); ++i)
            dst[tid + i*256] = src[tid + i*256];
    }

    u64 w2[HID/2];
    {
        const ulonglong2* wr = (const ulonglong2*)(W_hh + (size_t)row * HID);
        #pragma unroll
        for (int i = 0; i < HID/4; ++i) {
            ulonglong2 v = wr[i];
            w2[2*i+0] = v.x; w2[2*i+1] = v.y;
        }
    }
    float wih[INP];
    #pragma unroll
    for (int i = 0; i < INP; ++i) wih[i] = W_ih[row*INP + i];
    const float bias = b_ih[row] + b_hh[row];

    const float scale = (gate == 2) ? 1.0f : 0.5f;
    const float off   = (gate == 2) ? 0.0f : 0.5f;

    if (tid < HID) hbuf[0][tid] = 0.0f;
    float c = 0.0f;
    __syncthreads();

    int cur = 0;
    for (int t = 0; t < SEQ; ++t) {
        // x contribution for THIS step: independent of h -> overlaps the
        // dot-product chain below (both issued in the same region).
        const float* xt = xs + t*INP;
        float xacc = bias;
        #pragma unroll
        for (int i = 0; i < INP; ++i) xacc = fmaf(xt[i], wih[i], xacc);

        const ulonglong2* hv = (const ulonglong2*)hbuf[cur];
        u64 a[8];
        #pragma unroll
        for (int i = 0; i < 8; ++i) a[i] = 0ull;
        #pragma unroll
        for (int j = 0; j < 4; ++j) {
            ulonglong2 h0 = hv[4*j+0];
            ulonglong2 h1 = hv[4*j+1];
            ulonglong2 h2 = hv[4*j+2];
            ulonglong2 h3 = hv[4*j+3];
            a[0] = ffma2(h0.x, w2[8*j+0], a[0]);
            a[1] = ffma2(h0.y, w2[8*j+1], a[1]);
            a[2] = ffma2(h1.x, w2[8*j+2], a[2]);
            a[3] = ffma2(h1.y, w2[8*j+3], a[3]);
            a[4] = ffma2(h2.x, w2[8*j+4], a[4]);
            a[5] = ffma2(h2.y, w2[8*j+5], a[5]);
            a[6] = ffma2(h3.x, w2[8*j+6], a[6]);
            a[7] = ffma2(h3.y, w2[8*j+7], a[7]);
        }
        u64 s0 = fadd2(a[0], a[1]);
        u64 s1 = fadd2(a[2], a[3]);
        u64 s2 = fadd2(a[4], a[5]);
        u64 s3 = fadd2(a[6], a[7]);
        u64 s  = fadd2(fadd2(s0, s1), fadd2(s2, s3));
        float slo, shi; unpack2(s, slo, shi);
        float pre = xacc + slo + shi;

        float act = fmaf(scale, tanhf_fast(scale * pre), off);

        float ig = __shfl_sync(0xffffffffu, act, lb+0);
        float fg = __shfl_sync(0xffffffffu, act, lb+1);
        float gg = __shfl_sync(0xffffffffu, act, lb+2);
        float og = __shfl_sync(0xffffffffu, act, lb+3);

        c = fmaf(fg, c, ig*gg);
        float h = og * tanhf_fast(c);
        if (gate == 0) {
            hbuf[cur^1][hh] = h;
            hstage[(t>>4)&1][hh][t & 15] = h;
        }

        __syncthreads();
        cur ^= 1;

        if ((t & 15) == 15) {
            int wsel = (t >> 4) & 1;
            int k = tid >> 2;
            int j = (tid & 3) * 4;
            const float* hp = &hstage[wsel][k][j];
            float4 v = make_float4(hp[0], hp[1], hp[2], hp[3]);
            *(float4*)(g_hT + (size_t)k*MTOT + (size_t)b*SEQ + (t-15) + j) = v;
        }
    }
}

// ---------------------------------------------------------------------------
// FC on tensor cores (round-14 proven version, verbatim): tf32 MMA,
// cp.async double-buffered A, raw-fp32 A operands, 2 CTAs/SM.
// ---------------------------------------------------------------------------
#define AST   136
#define MLOOP 8

__global__ __launch_bounds__(256, 2)
void fc_mma_kernel(const float* __restrict__ W_fc,
                   const float* __restrict__ b_fc,
                   float* __restrict__ out)
{
    extern __shared__ u32 smemu[];
    u32*   Abuf[2] = { smemu, smemu + HID*AST };        // 2 x 34816 B
    uint4* Bs4 = (uint4*)(smemu + 2*HID*AST);           // [8][4][32] 16384 B
    float* bs  = (float*)(Bs4 + 8*4*32);                // [64] bias

    const int tid  = threadIdx.x;
    const int lane = tid & 31;
    const int warp = tid >> 5;
    const int lg   = lane >> 2;
    const int lt   = lane & 3;
    const int col0 = blockIdx.y * 64;
    const int ROW0 = blockIdx.x * (128 * MLOOP);

    #pragma unroll
    for (int q = 0; q < 4; ++q) {
        int idx = tid + q*256;
        int bl  = idx & 31;
        int jj  = (idx >> 5) & 3;
        int s   = idx >> 7;
        int kA  = s*8 + (bl & 3);
        int n1  = col0 + jj*16 + (bl >> 2);
        int n2  = n1 + 8;
        float fx=0.f, fy=0.f, fz=0.f, fw=0.f;
        if (n1 < OUTD) { fx = W_fc[n1*HID + kA]; fy = W_fc[n1*HID + kA + 4]; }
        if (n2 < OUTD) { fz = W_fc[n2*HID + kA]; fw = W_fc[n2*HID + kA + 4]; }
        Bs4[(s*4 + jj)*32 + bl] =
            make_uint4(cvt_tf32(fx), cvt_tf32(fy), cvt_tf32(fz), cvt_tf32(fw));
    }
    if (tid < 64) {
        int n = col0 + tid;
        bs[tid] = (n < OUTD) ? b_fc[n] : 0.0f;
    }

    int ak[8];
    #pragma unroll
    for (int l = 0; l < 8; ++l) ak[l] = (tid + l*256) >> 5;
    const int am = (tid & 31) * 4;

    {
        u32 sbase = (u32)__cvta_generic_to_shared(Abuf[0]);
        #pragma unroll
        for (int l = 0; l < 8; ++l)
            cp_async16(sbase + (u32)(ak[l]*AST + am)*4,
                       g_hT + (size_t)ak[l]*MTOT + ROW0 + am);
        CP_COMMIT();
    }

    for (int mt = 0; mt < MLOOP; ++mt) {
        u32* Acur = Abuf[mt & 1];
        u32* Anxt = Abuf[(mt & 1) ^ 1];

        CP_WAIT0();
        __syncthreads();

        if (mt + 1 < MLOOP) {
            u32 sbase = (u32)__cvta_generic_to_shared(Anxt);
            const int rn = ROW0 + (mt+1)*128;
            #pragma unroll
            for (int l = 0; l < 8; ++l)
                cp_async16(sbase + (u32)(ak[l]*AST + am)*4,
                           g_hT + (size_t)ak[l]*MTOT + rn + am);
            CP_COMMIT();
        }

        float d[8][4];
        #pragma unroll
        for (int j = 0; j < 8; ++j)
            #pragma unroll
            for (int p = 0; p < 4; ++p) d[j][p] = 0.f;

        #pragma unroll
        for (int s = 0; s < 8; ++s) {
            const int ka = s*8 + lt;
            const int mb = 16*warp + lg;
            u32 a0 = Acur[ ka      *AST + mb    ];
            u32 a1 = Acur[ ka      *AST + mb + 8];
            u32 a2 = Acur[(ka + 4) *AST + mb    ];
            u32 a3 = Acur[(ka + 4) *AST + mb + 8];
            #pragma unroll
            for (int jj = 0; jj < 4; ++jj) {
                uint4 bb = Bs4[(s*4 + jj)*32 + lane];
                mma_tf32(d[2*jj  ], a0, a1, a2, a3, bb.x, bb.y);
                mma_tf32(d[2*jj+1], a0, a1, a2, a3, bb.z, bb.w);
            }
        }

        const int r0 = ROW0 + mt*128 + 16*warp + lg;
        float* o0 = out + (size_t)r0 * OUTD;
        float* o1 = o0 + 8 * OUTD;
        #pragma unroll
        for (int j = 0; j < 8; ++j) {
            int njl = j*8 + lt*2;
            int nj  = col0 + njl;
            if (nj < OUTD) {
                float bx = bs[njl], by = bs[njl+1];
                float2 v0, v1;
                v0.x = d[j][0] + bx;  v0.y = d[j][1] + by;
                v1.x = d[j][2] + bx;  v1.y = d[j][3] + by;
                *(float2*)(o0 + nj) = v0;
                *(float2*)(o1 + nj) = v1;
            }
        }
        __syncthreads();
    }
}

extern "C" void kernel_launch(void* const* d_in, const int* in_sizes, int n_in,
                              void* d_out, int out_size)
{
    const float* x    = (const float*)d_in[0];
    const float* W_ih = (const float*)d_in[1];
    const float* W_hh = (const float*)d_in[2];
    const float* b_ih = (const float*)d_in[3];
    const float* b_hh = (const float*)d_in[4];
    const float* W_fc = (const float*)d_in[5];
    const float* b_fc = (const float*)d_in[6];
    float* out = (float*)d_out;

    static int smem_set = 0;
    const int dyn = 2*(HID*AST*4) + (8*4*32*16) + 256;   // 86272 B
    if (!smem_set) {
        cudaFuncSetAttribute(fc_mma_kernel,
                             cudaFuncAttributeMaxDynamicSharedMemorySize, dyn);
        smem_set = 1;
    }
    lstm_kernel<<<BATCH, 256>>>(x, W_ih, W_hh, b_ih, b_hh);
    fc_mma_kernel<<<dim3(MTOT/(128*MLOOP), 8), 256, dyn>>>(W_fc, b_fc, out);
}